// round 14
// baseline (speedup 1.0000x reference)
#include <cuda_runtime.h>
#include <cstdint>
#include <cstddef>

#define TDIM 2048
#define SDIM 2048
#define BSZ  2
#define EDIM 1024
#define NH   16
#define HD   64
#define NZ   (BSZ*NH)          // 32

#define SCALING_F  0.125f      // 64^-0.5
#define D_THRESH_F 3.8918202981106265f   // log(2000/40 - 1) = log(49)

// ---------------- scratch (__device__ globals; no runtime allocs) ------------
__device__ float g_q  [(size_t)NZ * TDIM * HD];     // [z][t][d]
__device__ float g_k  [(size_t)NZ * SDIM * HD];     // [z][s][d]
__device__ float g_v  [(size_t)NZ * SDIM * HD];     // [z][s][d]
__device__ float g_mid[(size_t)TDIM * BSZ * EDIM];  // pre-output-proj attn
__device__ float g_sink[(size_t)TDIM * BSZ * EDIM]; // sink if out lacks attn

// ---------------- helpers ----------------------------------------------------
__device__ __forceinline__ uint32_t f2tf32(float x) {   // RN fp32->tf32 bits
    uint32_t u = __float_as_uint(x);
    return (u + 0x1000u) & 0xFFFFE000u;
}

__device__ __forceinline__ void mma_tf32(float* d, const uint32_t* a, const uint32_t* b) {
    asm volatile(
        "mma.sync.aligned.m16n8k8.row.col.f32.tf32.tf32.f32 "
        "{%0,%1,%2,%3}, {%4,%5,%6,%7}, {%8,%9}, {%0,%1,%2,%3};\n"
        : "+f"(d[0]), "+f"(d[1]), "+f"(d[2]), "+f"(d[3])
        : "r"(a[0]), "r"(a[1]), "r"(a[2]), "r"(a[3]), "r"(b[0]), "r"(b[1]));
}

__device__ __forceinline__ uint32_t s2u(const void* p) {
    return (uint32_t)__cvta_generic_to_shared(p);
}
__device__ __forceinline__ void cpa16(uint32_t dst, const void* src) {
    asm volatile("cp.async.cg.shared.global [%0], [%1], 16;\n" :: "r"(dst), "l"(src) : "memory");
}
#define CPA_COMMIT() asm volatile("cp.async.commit_group;\n" ::: "memory")
#define CPA_WAIT0()  asm volatile("cp.async.wait_group 0;\n" ::: "memory")
#define CPA_WAIT1()  asm volatile("cp.async.wait_group 1;\n" ::: "memory")

// ---------------- projection GEMM body: C = X @ W^T + bias -------------------
// 1-barrier double buffer: wait0 -> sync -> issue stage(c+1) -> compute(c).
// stage(c+1) overwrites the buffer compute(c-1) used; the sync at top of
// iter c guarantees all warps finished compute(c-1).
#define GS 36                                 // padded k-stride (floats)
#define GEMM_SMEM (4 * 128 * GS * 4)          // As[2]+Bs[2] = 73728 B

__device__ __forceinline__ void gemm_body(
    const float* __restrict__ X, const float* __restrict__ W,
    const float* __restrict__ bias, float* __restrict__ out, int mode,
    float* gsm)
{
    float* As = gsm;                  // [2][128][GS]
    float* Bs = gsm + 2 * 128 * GS;   // [2][128][GS]

    const int tid  = threadIdx.x;
    const int lane = tid & 31, wid = tid >> 5;
    const int wm = wid >> 2, wn = wid & 3;      // 2 x 4 warp grid, 64x32 warp tile
    const int lr = lane >> 2, lc = lane & 3;
    const int rowBase = blockIdx.y * 128;
    const int colBase = blockIdx.x * 128;

    float acc[4][4][4];
    #pragma unroll
    for (int i = 0; i < 4; i++)
        #pragma unroll
        for (int j = 0; j < 4; j++)
            #pragma unroll
            for (int r = 0; r < 4; r++) acc[i][j][r] = 0.f;

    const float* Ag = X + (size_t)rowBase * EDIM;
    const float* Bg = W + (size_t)colBase * EDIM;

    auto stage = [&](int k0, int buf) {
        #pragma unroll
        for (int i = 0; i < 4; i++) {
            int idx = tid + i * 256;          // float4 id 0..1023
            int row = idx >> 3, c4 = (idx & 7) * 4;
            cpa16(s2u(&As[(buf * 128 + row) * GS + c4]),
                  Ag + (size_t)row * EDIM + k0 + c4);
            cpa16(s2u(&Bs[(buf * 128 + row) * GS + c4]),
                  Bg + (size_t)row * EDIM + k0 + c4);
        }
        CPA_COMMIT();
    };

    stage(0, 0);
    for (int c = 0; c < 32; c++) {
        CPA_WAIT0();
        __syncthreads();
        if (c < 31) stage((c + 1) * 32, (c + 1) & 1);
        const float* Ab = As + (c & 1) * 128 * GS;
        const float* Bb = Bs + (c & 1) * 128 * GS;
        #pragma unroll
        for (int kk = 0; kk < 4; kk++) {
            const int ko = kk * 8;
            uint32_t a[4][4], b[4][2];
            #pragma unroll
            for (int mf = 0; mf < 4; mf++) {
                int m = wm * 64 + mf * 16;
                a[mf][0] = f2tf32(Ab[(m + lr    ) * GS + ko + lc    ]);
                a[mf][1] = f2tf32(Ab[(m + lr + 8) * GS + ko + lc    ]);
                a[mf][2] = f2tf32(Ab[(m + lr    ) * GS + ko + lc + 4]);
                a[mf][3] = f2tf32(Ab[(m + lr + 8) * GS + ko + lc + 4]);
            }
            #pragma unroll
            for (int nf = 0; nf < 4; nf++) {
                int n = wn * 32 + nf * 8;
                b[nf][0] = f2tf32(Bb[(n + lr) * GS + ko + lc    ]);
                b[nf][1] = f2tf32(Bb[(n + lr) * GS + ko + lc + 4]);
            }
            #pragma unroll
            for (int mf = 0; mf < 4; mf++)
                #pragma unroll
                for (int nf = 0; nf < 4; nf++)
                    mma_tf32(acc[mf][nf], a[mf], b[nf]);
        }
    }

    #pragma unroll
    for (int mf = 0; mf < 4; mf++) {
        #pragma unroll
        for (int nf = 0; nf < 4; nf++) {
            #pragma unroll
            for (int rp = 0; rp < 2; rp++) {
                int row = rowBase + wm * 64 + mf * 16 + lr + rp * 8;
                int col = colBase + wn * 32 + nf * 8 + 2 * lc;
                float v0 = acc[mf][nf][rp * 2 + 0] + bias[col];
                float v1 = acc[mf][nf][rp * 2 + 1] + bias[col + 1];
                if (mode == 0) { v0 *= SCALING_F; v1 *= SCALING_F; }
                if (mode <= 1) {
                    int t = row >> 1, bb = row & 1;          // row = t*B + b
                    int z = bb * NH + (col >> 6);            // z = b*H + h
                    *(float2*)&out[((size_t)(z * TDIM + t) << 6) + (col & 63)]
                        = make_float2(v0, v1);
                } else {
                    *(float2*)&out[(size_t)row * EDIM + col] = make_float2(v0, v1);
                }
            }
        }
    }
}

// fused q/k/v projections in ONE launch: gridDim.z = 3 selects the problem
__global__ __launch_bounds__(256, 2) void qkv_gemm_kernel(
    const float* Xq, const float* Xk, const float* Xv,
    const float* Wq, const float* Wk, const float* Wv,
    const float* bq, const float* bk, const float* bv,
    float* oq, float* ok, float* ov)
{
    extern __shared__ float gsm[];
    const int zz = blockIdx.z;
    const float* X = (zz == 0) ? Xq : (zz == 1) ? Xk : Xv;
    const float* W = (zz == 0) ? Wq : (zz == 1) ? Wk : Wv;
    const float* B = (zz == 0) ? bq : (zz == 1) ? bk : bv;
    float*       O = (zz == 0) ? oq : (zz == 1) ? ok : ov;
    gemm_body(X, W, B, O, (zz == 0) ? 0 : 1, gsm);
}

__global__ __launch_bounds__(256, 2) void gemm_tf32_kernel(
    const float* __restrict__ X, const float* __restrict__ W,
    const float* __restrict__ bias, float* __restrict__ out, int mode)
{
    extern __shared__ float gsm[];
    gemm_body(X, W, bias, out, mode, gsm);
}

// ---------------- score GEMM: raw scores = Q @ K^T ---------------------------
// Per CTA: one z, 128 t-rows x 128 s-cols, K-dim = 64 single shot.
// Writes RAW scores into the weights output buffer (normalized later in place).
#define QS2 68
#define SCORE_SMEM (2 * 128 * QS2 * 4)        // 69632 B -> 2 CTAs/SM

__global__ __launch_bounds__(256, 2) void score_gemm_kernel(
    const float* __restrict__ qs, const float* __restrict__ ks,
    float* __restrict__ wout)
{
    extern __shared__ float ssm[];
    float* Qs = ssm;               // [128][QS2]
    float* Ks = ssm + 128 * QS2;   // [128][QS2]

    const int tid  = threadIdx.x;
    const int lane = tid & 31, wid = tid >> 5;
    const int wm = wid >> 2, wn = wid & 3;      // 2 x 4 warps, 64x32 tiles
    const int lr = lane >> 2, lc = lane & 3;
    const int s0 = blockIdx.x * 128;
    const int t0 = blockIdx.y * 128;
    const int z  = blockIdx.z;

    const float* qg = qs + ((size_t)z * TDIM + t0) * HD;
    const float* kg = ks + ((size_t)z * SDIM + s0) * HD;

    #pragma unroll
    for (int i = 0; i < 8; i++) {             // 2048 float4 per tile
        int idx = tid + i * 256;
        int row = idx >> 4, c4 = (idx & 15) * 4;
        cpa16(s2u(&Qs[row * QS2 + c4]), qg + (size_t)row * HD + c4);
        cpa16(s2u(&Ks[row * QS2 + c4]), kg + (size_t)row * HD + c4);
    }
    CPA_COMMIT(); CPA_WAIT0();
    __syncthreads();

    float acc[4][4][4];
    #pragma unroll
    for (int i = 0; i < 4; i++)
        #pragma unroll
        for (int j = 0; j < 4; j++)
            #pragma unroll
            for (int r = 0; r < 4; r++) acc[i][j][r] = 0.f;

    #pragma unroll
    for (int kk = 0; kk < 8; kk++) {
        const int ko = kk * 8;
        uint32_t a[4][4], b[4][2];
        #pragma unroll
        for (int mf = 0; mf < 4; mf++) {
            int m = wm * 64 + mf * 16;
            a[mf][0] = f2tf32(Qs[(m + lr    ) * QS2 + ko + lc    ]);
            a[mf][1] = f2tf32(Qs[(m + lr + 8) * QS2 + ko + lc    ]);
            a[mf][2] = f2tf32(Qs[(m + lr    ) * QS2 + ko + lc + 4]);
            a[mf][3] = f2tf32(Qs[(m + lr + 8) * QS2 + ko + lc + 4]);
        }
        #pragma unroll
        for (int nf = 0; nf < 4; nf++) {
            int n = wn * 32 + nf * 8;
            b[nf][0] = f2tf32(Ks[(n + lr) * QS2 + ko + lc    ]);
            b[nf][1] = f2tf32(Ks[(n + lr) * QS2 + ko + lc + 4]);
        }
        #pragma unroll
        for (int mf = 0; mf < 4; mf++)
            #pragma unroll
            for (int nf = 0; nf < 4; nf++)
                mma_tf32(acc[mf][nf], a[mf], b[nf]);
    }

    float* wbase = wout + ((size_t)z * TDIM + t0) * SDIM;
    #pragma unroll
    for (int mf = 0; mf < 4; mf++) {
        #pragma unroll
        for (int nf = 0; nf < 4; nf++) {
            #pragma unroll
            for (int rp = 0; rp < 2; rp++) {
                int row = wm * 64 + mf * 16 + lr + rp * 8;
                int col = s0 + wn * 32 + nf * 8 + 2 * lc;
                *(float2*)&wbase[(size_t)row * SDIM + col]
                    = make_float2(acc[mf][nf][rp*2], acc[mf][nf][rp*2+1]);
            }
        }
    }
}

// ---------------- softmax: in-place mask + threshold + normalize -------------
// Warp per row; 8 rows per CTA. Row (2048 fp32) held in 64 regs per lane.
__global__ __launch_bounds__(256) void softmax_kernel(
    float* __restrict__ wts, const int* __restrict__ mask)
{
    const int lane = threadIdx.x & 31, w = threadIdx.x >> 5;
    const int t = blockIdx.x * 8 + w;
    const int z = blockIdx.y;
    const float NEG = __int_as_float(0xff800000);

    float* row = wts + ((size_t)z * TDIM + t) * SDIM;
    const int* mrow = mask + (size_t)t * SDIM;

    float sv[64];
    float mx = NEG;
    #pragma unroll
    for (int j = 0; j < 16; j++) {
        int col = j * 128 + lane * 4;
        float4 s = *(const float4*)&row[col];
        int4  mm = *(const int4*)&mrow[col];
        sv[4*j+0] = mm.x ? s.x : NEG;
        sv[4*j+1] = mm.y ? s.y : NEG;
        sv[4*j+2] = mm.z ? s.z : NEG;
        sv[4*j+3] = mm.w ? s.w : NEG;
        mx = fmaxf(mx, fmaxf(fmaxf(sv[4*j], sv[4*j+1]), fmaxf(sv[4*j+2], sv[4*j+3])));
    }
    #pragma unroll
    for (int off = 16; off; off >>= 1)
        mx = fmaxf(mx, __shfl_xor_sync(0xffffffffu, mx, off));

    float sum = 0.f;
    #pragma unroll
    for (int j = 0; j < 64; j++) {
        float d = sv[j] - mx;
        float e = (d >= -D_THRESH_F) ? __expf(d) : 0.f;
        sv[j] = e;
        sum += e;
    }
    #pragma unroll
    for (int off = 16; off; off >>= 1)
        sum += __shfl_xor_sync(0xffffffffu, sum, off);
    const float ri = 1.f / sum;

    #pragma unroll
    for (int j = 0; j < 16; j++) {
        int col = j * 128 + lane * 4;
        *(float4*)&row[col] = make_float4(sv[4*j]*ri, sv[4*j+1]*ri,
                                          sv[4*j+2]*ri, sv[4*j+3]*ri);
    }
}

// ---------------- AV GEMM: attn_mid = weights @ V ----------------------------
// 1-barrier double buffer (same pattern as gemm_body).
#define PS 68
#define AV_SMEM ((2*128*PS + 2*64*PS) * 4)     // 104448 B

__global__ __launch_bounds__(256, 2) void av_gemm_kernel(
    const float* __restrict__ wts, const float* __restrict__ vs,
    float* __restrict__ attn_mid)
{
    extern __shared__ float avm[];
    float* Ps = avm;                  // [2][128][PS]
    float* Vs = avm + 2 * 128 * PS;   // [2][64][PS]

    const int tid  = threadIdx.x;
    const int lane = tid & 31, wid = tid >> 5;
    const int wm = wid >> 1, wn = wid & 1;       // 4 x 2 warps, 32x32 tiles
    const int lr = lane >> 2, lc = lane & 3;
    const int t0 = blockIdx.x * 128;
    const int z  = blockIdx.y;

    const float* pbase = wts + (size_t)z * TDIM * SDIM + (size_t)t0 * SDIM;
    const float* vbase = vs  + (size_t)z * SDIM * HD;

    float acc[2][4][4];
    #pragma unroll
    for (int i = 0; i < 2; i++)
        #pragma unroll
        for (int j = 0; j < 4; j++)
            #pragma unroll
            for (int r = 0; r < 4; r++) acc[i][j][r] = 0.f;

    auto stage = [&](int s0, int buf) {
        #pragma unroll
        for (int i = 0; i < 8; i++) {
            int idx = tid + i * 256;
            int row = idx >> 4, c4 = (idx & 15) * 4;
            cpa16(s2u(&Ps[(buf * 128 + row) * PS + c4]),
                  pbase + (size_t)row * SDIM + s0 + c4);
        }
        #pragma unroll
        for (int i = 0; i < 4; i++) {
            int idx = tid + i * 256;
            int row = idx >> 4, c4 = (idx & 15) * 4;
            cpa16(s2u(&Vs[(buf * 64 + row) * PS + c4]),
                  vbase + (size_t)(s0 + row) * HD + c4);
        }
        CPA_COMMIT();
    };

    stage(0, 0);
    for (int c = 0; c < 32; c++) {
        CPA_WAIT0();
        __syncthreads();
        if (c < 31) stage((c + 1) * 64, (c + 1) & 1);
        const float* Pb = Ps + (c & 1) * 128 * PS;
        const float* Vb = Vs + (c & 1) * 64 * PS;
        #pragma unroll
        for (int kk = 0; kk < 8; kk++) {
            const int ko = kk * 8;
            uint32_t a[2][4], b[4][2];
            #pragma unroll
            for (int mf = 0; mf < 2; mf++) {
                int m = wm * 32 + mf * 16;
                a[mf][0] = f2tf32(Pb[(m + lr    ) * PS + ko + lc    ]);
                a[mf][1] = f2tf32(Pb[(m + lr + 8) * PS + ko + lc    ]);
                a[mf][2] = f2tf32(Pb[(m + lr    ) * PS + ko + lc + 4]);
                a[mf][3] = f2tf32(Pb[(m + lr + 8) * PS + ko + lc + 4]);
            }
            #pragma unroll
            for (int nf = 0; nf < 4; nf++) {
                int n = wn * 32 + nf * 8;
                b[nf][0] = f2tf32(Vb[(ko + lc    ) * PS + n + lr]);
                b[nf][1] = f2tf32(Vb[(ko + lc + 4) * PS + n + lr]);
            }
            #pragma unroll
            for (int mf = 0; mf < 2; mf++)
                #pragma unroll
                for (int nf = 0; nf < 4; nf++)
                    mma_tf32(acc[mf][nf], a[mf], b[nf]);
        }
    }

    const int bb = z >> 4, hh = z & 15;
    #pragma unroll
    for (int mf = 0; mf < 2; mf++) {
        #pragma unroll
        for (int nf = 0; nf < 4; nf++) {
            #pragma unroll
            for (int rp = 0; rp < 2; rp++) {
                int t   = t0 + wm * 32 + mf * 16 + lr + rp * 8;
                int col = wn * 32 + nf * 8 + 2 * lc;
                *(float2*)&attn_mid[((size_t)(t * BSZ + bb)) * EDIM + hh * 64 + col]
                    = make_float2(acc[mf][nf][rp*2], acc[mf][nf][rp*2+1]);
            }
        }
    }
}

// ---------------- fallback attention (write_w == 0 only) ---------------------
#define SC_STRIDE 2052
#define KV_STRIDE 72
#define SC_FLOATS (16 * SC_STRIDE)
#define KV_FLOATS (2 * 128 * KV_STRIDE)
#define ATTN_SMEM ((SC_FLOATS + KV_FLOATS + 1024 + 256 + 16 + 16) * 4)

__global__ __launch_bounds__(512, 1) void attn_kernel(
    const float* __restrict__ qs, const float* __restrict__ ks,
    const float* __restrict__ vs, const int* __restrict__ mask,
    float* __restrict__ attn_mid)
{
    extern __shared__ float sm[];
    float* sc     = sm;
    float* kvb    = sm + SC_FLOATS;
    float* pacc   = kvb + KV_FLOATS;
    float* red    = pacc + 1024;
    float* rowmax = red + 256;
    float* rinvs  = rowmax + 16;

    const int tid = threadIdx.x, lane = tid & 31, w = tid >> 5;
    const int lr = lane >> 2, lc = lane & 3;
    const int t0 = blockIdx.x * 16;
    const int z  = blockIdx.y;
    const float NEG = __int_as_float(0xff800000);

    uint32_t aq[8][4];
    {
        const float* qg = qs + ((size_t)(z * TDIM + t0)) * HD;
        #pragma unroll
        for (int kk = 0; kk < 8; kk++) {
            aq[kk][0] = f2tf32(qg[ lr      * 64 + kk*8 + lc    ]);
            aq[kk][1] = f2tf32(qg[(lr + 8) * 64 + kk*8 + lc    ]);
            aq[kk][2] = f2tf32(qg[ lr      * 64 + kk*8 + lc + 4]);
            aq[kk][3] = f2tf32(qg[(lr + 8) * 64 + kk*8 + lc + 4]);
        }
    }

    auto stageKV = [&](const float* src, int s0, int buf) {
        #pragma unroll
        for (int i = 0; i < 4; i++) {
            int idx = tid + i * 512;
            int row = idx >> 4, c4 = (idx & 15) * 4;
            cpa16(s2u(&kvb[(buf * 128 + row) * KV_STRIDE + c4]),
                  src + (size_t)(s0 + row) * HD + c4);
        }
        CPA_COMMIT();
    };

    float mx0 = NEG, mx1 = NEG;
    const float* kbase = ks + (size_t)z * SDIM * HD;
    stageKV(kbase, 0, 0);
    for (int c = 0; c < 16; c++) {
        const int s0 = c * 128;
        CPA_WAIT0();
        __syncthreads();
        if (c < 15) stageKV(kbase, s0 + 128, (c + 1) & 1);

        const int col0 = s0 + w * 8 + 2 * lc;
        int2 m0 = *(const int2*)(mask + (size_t)(t0 + lr    ) * SDIM + col0);
        int2 m1 = *(const int2*)(mask + (size_t)(t0 + lr + 8) * SDIM + col0);

        const float* kb = kvb + (c & 1) * 128 * KV_STRIDE;
        float cacc[4] = {0.f, 0.f, 0.f, 0.f};
        #pragma unroll
        for (int kk = 0; kk < 8; kk++) {
            uint32_t b[2];
            b[0] = f2tf32(kb[(w * 8 + lr) * KV_STRIDE + kk*8 + lc    ]);
            b[1] = f2tf32(kb[(w * 8 + lr) * KV_STRIDE + kk*8 + lc + 4]);
            mma_tf32(cacc, aq[kk], b);
        }
        float v0 = (m0.x == 0) ? NEG : cacc[0];
        float v1 = (m0.y == 0) ? NEG : cacc[1];
        float v2 = (m1.x == 0) ? NEG : cacc[2];
        float v3 = (m1.y == 0) ? NEG : cacc[3];
        *(float2*)&sc[ lr      * SC_STRIDE + col0] = make_float2(v0, v1);
        *(float2*)&sc[(lr + 8) * SC_STRIDE + col0] = make_float2(v2, v3);
        mx0 = fmaxf(mx0, fmaxf(v0, v1));
        mx1 = fmaxf(mx1, fmaxf(v2, v3));
    }

    mx0 = fmaxf(mx0, __shfl_xor_sync(0xffffffffu, mx0, 1));
    mx0 = fmaxf(mx0, __shfl_xor_sync(0xffffffffu, mx0, 2));
    mx1 = fmaxf(mx1, __shfl_xor_sync(0xffffffffu, mx1, 1));
    mx1 = fmaxf(mx1, __shfl_xor_sync(0xffffffffu, mx1, 2));
    if (lc == 0) { red[w * 16 + lr] = mx0; red[w * 16 + lr + 8] = mx1; }
    __syncthreads();
    if (tid < 16) {
        float m = red[tid];
        #pragma unroll
        for (int i = 1; i < 16; i++) m = fmaxf(m, red[i * 16 + tid]);
        rowmax[tid] = m;
    }
    __syncthreads();

    {
        const int row = w;
        const float m = rowmax[row];
        float sum = 0.f;
        #pragma unroll 4
        for (int col = lane * 4; col < SDIM; col += 128) {
            float4 s = *(float4*)&sc[row * SC_STRIDE + col];
            float e0 = (s.x - m >= -D_THRESH_F) ? __expf(s.x - m) : 0.f;
            float e1 = (s.y - m >= -D_THRESH_F) ? __expf(s.y - m) : 0.f;
            float e2 = (s.z - m >= -D_THRESH_F) ? __expf(s.z - m) : 0.f;
            float e3 = (s.w - m >= -D_THRESH_F) ? __expf(s.w - m) : 0.f;
            *(float4*)&sc[row * SC_STRIDE + col] = make_float4(e0, e1, e2, e3);
            sum += (e0 + e1) + (e2 + e3);
        }
        #pragma unroll
        for (int off = 16; off; off >>= 1)
            sum += __shfl_xor_sync(0xffffffffu, sum, off);
        if (lane == 0) rinvs[row] = 1.f / sum;
    }

    __syncthreads();
    const int nOct  = w & 7;
    const int kHalf = w >> 3;
    float acc[4] = {0.f, 0.f, 0.f, 0.f};
    const float* vbase = vs + (size_t)z * SDIM * HD;
    stageKV(vbase, 0, 0);
    for (int c = 0; c < 16; c++) {
        const int s0 = c * 128;
        CPA_WAIT0();
        __syncthreads();
        if (c < 15) stageKV(vbase, s0 + 128, (c + 1) & 1);
        const float* vb = kvb + (c & 1) * 128 * KV_STRIDE;
        #pragma unroll
        for (int j = 0; j < 8; j++) {
            const int kk = kHalf * 8 + j;
            const int kg = s0 + kk * 8;
            uint32_t a[4], b[2];
            a[0] = f2tf32(sc[ lr      * SC_STRIDE + kg + lc    ]);
            a[1] = f2tf32(sc[(lr + 8) * SC_STRIDE + kg + lc    ]);
            a[2] = f2tf32(sc[ lr      * SC_STRIDE + kg + lc + 4]);
            a[3] = f2tf32(sc[(lr + 8) * SC_STRIDE + kg + lc + 4]);
            b[0] = f2tf32(vb[(kk*8 + lc    ) * KV_STRIDE + nOct * 8 + lr]);
            b[1] = f2tf32(vb[(kk*8 + lc + 4) * KV_STRIDE + nOct * 8 + lr]);
            mma_tf32(acc, a, b);
        }
    }
    if (kHalf == 1) {
        #pragma unroll
        for (int r = 0; r < 4; r++) pacc[nOct * 128 + lane * 4 + r] = acc[r];
    }
    __syncthreads();
    if (kHalf == 0) {
        const int bb = z >> 4, hh = z & 15;
        #pragma unroll
        for (int rp = 0; rp < 2; rp++) {
            int row  = lr + rp * 8;
            int colh = nOct * 8 + 2 * lc;
            float ri = rinvs[row];
            float v0 = (acc[rp*2+0] + pacc[nOct * 128 + lane * 4 + rp*2+0]) * ri;
            float v1 = (acc[rp*2+1] + pacc[nOct * 128 + lane * 4 + rp*2+1]) * ri;
            int t = t0 + row;
            *(float2*)&attn_mid[((size_t)(t * BSZ + bb)) * EDIM + hh * 64 + colh]
                = make_float2(v0, v1);
        }
    }
}

// ---------------- launcher ----------------------------------------------------
extern "C" void kernel_launch(void* const* d_in, const int* in_sizes, int n_in,
                              void* d_out, int out_size) {
    const float* query = (const float*)d_in[0];
    const float* key   = (const float*)d_in[1];
    const float* value = (const float*)d_in[2];
    const int*   mask  = (const int*)  d_in[3];
    const float* Wq = (const float*)d_in[4];
    const float* bq = (const float*)d_in[5];
    const float* Wk = (const float*)d_in[6];
    const float* bk = (const float*)d_in[7];
    const float* Wv = (const float*)d_in[8];
    const float* bv = (const float*)d_in[9];
    const float* Wo = (const float*)d_in[10];
    const float* bo = (const float*)d_in[11];

    float *pq, *pk, *pv, *pmid, *psink;
    cudaGetSymbolAddress((void**)&pq,    g_q);
    cudaGetSymbolAddress((void**)&pk,    g_k);
    cudaGetSymbolAddress((void**)&pv,    g_v);
    cudaGetSymbolAddress((void**)&pmid,  g_mid);
    cudaGetSymbolAddress((void**)&psink, g_sink);

    const long long ATTN_N = (long long)TDIM * BSZ * EDIM;       // 4,194,304
    const long long WTS_N  = (long long)NZ * TDIM * SDIM;        // 134,217,728
    float* out = (float*)d_out;
    float* out_attn = out;
    float* out_w    = nullptr;
    int write_w = 0;
    long long osz = (long long)out_size;
    if (osz >= ATTN_N + WTS_N)      { out_attn = out; out_w = out + ATTN_N; write_w = 1; }
    else if (osz == WTS_N)          { out_attn = psink; out_w = out; write_w = 1; }
    else                            { out_attn = out; write_w = 0; out_w = psink; }

    cudaFuncSetAttribute(qkv_gemm_kernel,
                         cudaFuncAttributeMaxDynamicSharedMemorySize, GEMM_SMEM);
    cudaFuncSetAttribute(gemm_tf32_kernel,
                         cudaFuncAttributeMaxDynamicSharedMemorySize, GEMM_SMEM);
    cudaFuncSetAttribute(score_gemm_kernel,
                         cudaFuncAttributeMaxDynamicSharedMemorySize, SCORE_SMEM);
    cudaFuncSetAttribute(attn_kernel,
                         cudaFuncAttributeMaxDynamicSharedMemorySize, ATTN_SMEM);
    cudaFuncSetAttribute(av_gemm_kernel,
                         cudaFuncAttributeMaxDynamicSharedMemorySize, AV_SMEM);

    dim3 gq(EDIM / 128, (TDIM * BSZ) / 128, 3);   // (8, 32, 3)
    qkv_gemm_kernel<<<gq, 256, GEMM_SMEM>>>(
        query, key, value, Wq, Wk, Wv, bq, bk, bv, pq, pk, pv);

    if (write_w) {
        score_gemm_kernel<<<dim3(SDIM / 128, TDIM / 128, NZ), 256, SCORE_SMEM>>>(
            pq, pk, out_w);
        softmax_kernel<<<dim3(TDIM / 8, NZ), 256>>>(out_w, mask);
        av_gemm_kernel<<<dim3(TDIM / 128, NZ), 256, AV_SMEM>>>(out_w, pv, pmid);
    } else {
        attn_kernel<<<dim3(TDIM / 16, NZ), 512, ATTN_SMEM>>>(
            pq, pk, pv, mask, pmid);
    }

    dim3 gg(EDIM / 128, (TDIM * BSZ) / 128);   // (8, 32)
    gemm_tf32_kernel<<<gg, 256, GEMM_SMEM>>>(pmid, Wo, bo, out_attn, 2);
}

// round 17
// speedup vs baseline: 1.4458x; 1.4458x over previous
#include <cuda_runtime.h>
#include <cstdint>
#include <cstddef>

#define TDIM 2048
#define SDIM 2048
#define BSZ  2
#define EDIM 1024
#define NH   16
#define HD   64
#define NZ   (BSZ*NH)          // 32

#define SCALING_F  0.125f      // 64^-0.5
#define D_THRESH_F 3.8918202981106265f   // log(2000/40 - 1) = log(49)

// ---------------- scratch (__device__ globals; no runtime allocs) ------------
__device__ float g_q  [(size_t)NZ * TDIM * HD];     // [z][t][d]
__device__ float g_k  [(size_t)NZ * SDIM * HD];     // [z][s][d]
__device__ float g_v  [(size_t)NZ * SDIM * HD];     // [z][s][d]
__device__ float g_mid[(size_t)TDIM * BSZ * EDIM];  // pre-output-proj attn
__device__ float g_sink[(size_t)TDIM * BSZ * EDIM]; // sink if out lacks attn

// ---------------- helpers ----------------------------------------------------
__device__ __forceinline__ uint32_t f2tf32(float x) {   // RN fp32->tf32 bits
    uint32_t u = __float_as_uint(x);
    return (u + 0x1000u) & 0xFFFFE000u;
}

__device__ __forceinline__ void mma_tf32(float* d, const uint32_t* a, const uint32_t* b) {
    asm volatile(
        "mma.sync.aligned.m16n8k8.row.col.f32.tf32.tf32.f32 "
        "{%0,%1,%2,%3}, {%4,%5,%6,%7}, {%8,%9}, {%0,%1,%2,%3};\n"
        : "+f"(d[0]), "+f"(d[1]), "+f"(d[2]), "+f"(d[3])
        : "r"(a[0]), "r"(a[1]), "r"(a[2]), "r"(a[3]), "r"(b[0]), "r"(b[1]));
}

__device__ __forceinline__ uint32_t s2u(const void* p) {
    return (uint32_t)__cvta_generic_to_shared(p);
}
__device__ __forceinline__ void cpa16(uint32_t dst, const void* src) {
    asm volatile("cp.async.cg.shared.global [%0], [%1], 16;\n" :: "r"(dst), "l"(src) : "memory");
}
#define CPA_COMMIT() asm volatile("cp.async.commit_group;\n" ::: "memory")
#define CPA_WAIT0()  asm volatile("cp.async.wait_group 0;\n" ::: "memory")
#define CPA_WAIT1()  asm volatile("cp.async.wait_group 1;\n" ::: "memory")

// ---------------- projection GEMM body: C = X @ W^T + bias -------------------
// R10-validated 2-sync double-buffer pattern. DO NOT change the loop shape.
#define GS 36                                 // padded k-stride (floats)
#define GEMM_SMEM (4 * 128 * GS * 4)          // As[2]+Bs[2] = 73728 B

__device__ __forceinline__ void gemm_body(
    const float* __restrict__ X, const float* __restrict__ W,
    const float* __restrict__ bias, float* __restrict__ out, int mode,
    float* gsm, int bx, int by)
{
    float* As = gsm;                  // [2][128][GS]
    float* Bs = gsm + 2 * 128 * GS;   // [2][128][GS]

    const int tid  = threadIdx.x;
    const int lane = tid & 31, wid = tid >> 5;
    const int wm = wid >> 2, wn = wid & 3;      // 2 x 4 warp grid, 64x32 warp tile
    const int lr = lane >> 2, lc = lane & 3;
    const int rowBase = by * 128;
    const int colBase = bx * 128;

    float acc[4][4][4];
    #pragma unroll
    for (int i = 0; i < 4; i++)
        #pragma unroll
        for (int j = 0; j < 4; j++)
            #pragma unroll
            for (int r = 0; r < 4; r++) acc[i][j][r] = 0.f;

    const float* Ag = X + (size_t)rowBase * EDIM;
    const float* Bg = W + (size_t)colBase * EDIM;

    auto stage = [&](int k0, int buf) {
        #pragma unroll
        for (int i = 0; i < 4; i++) {
            int idx = tid + i * 256;          // float4 id 0..1023
            int row = idx >> 3, c4 = (idx & 7) * 4;
            cpa16(s2u(&As[(buf * 128 + row) * GS + c4]),
                  Ag + (size_t)row * EDIM + k0 + c4);
            cpa16(s2u(&Bs[(buf * 128 + row) * GS + c4]),
                  Bg + (size_t)row * EDIM + k0 + c4);
        }
        CPA_COMMIT();
    };

    stage(0, 0);
    for (int c = 0; c < 32; c++) {
        __syncthreads();
        if (c < 31) { stage((c + 1) * 32, (c + 1) & 1); CPA_WAIT1(); }
        else        { CPA_WAIT0(); }
        __syncthreads();
        const float* Ab = As + (c & 1) * 128 * GS;
        const float* Bb = Bs + (c & 1) * 128 * GS;
        #pragma unroll
        for (int kk = 0; kk < 4; kk++) {
            const int ko = kk * 8;
            uint32_t a[4][4], b[4][2];
            #pragma unroll
            for (int mf = 0; mf < 4; mf++) {
                int m = wm * 64 + mf * 16;
                a[mf][0] = f2tf32(Ab[(m + lr    ) * GS + ko + lc    ]);
                a[mf][1] = f2tf32(Ab[(m + lr + 8) * GS + ko + lc    ]);
                a[mf][2] = f2tf32(Ab[(m + lr    ) * GS + ko + lc + 4]);
                a[mf][3] = f2tf32(Ab[(m + lr + 8) * GS + ko + lc + 4]);
            }
            #pragma unroll
            for (int nf = 0; nf < 4; nf++) {
                int n = wn * 32 + nf * 8;
                b[nf][0] = f2tf32(Bb[(n + lr) * GS + ko + lc    ]);
                b[nf][1] = f2tf32(Bb[(n + lr) * GS + ko + lc + 4]);
            }
            #pragma unroll
            for (int mf = 0; mf < 4; mf++)
                #pragma unroll
                for (int nf = 0; nf < 4; nf++)
                    mma_tf32(acc[mf][nf], a[mf], b[nf]);
        }
    }

    #pragma unroll
    for (int mf = 0; mf < 4; mf++) {
        #pragma unroll
        for (int nf = 0; nf < 4; nf++) {
            #pragma unroll
            for (int rp = 0; rp < 2; rp++) {
                int row = rowBase + wm * 64 + mf * 16 + lr + rp * 8;
                int col = colBase + wn * 32 + nf * 8 + 2 * lc;
                float v0 = acc[mf][nf][rp * 2 + 0] + bias[col];
                float v1 = acc[mf][nf][rp * 2 + 1] + bias[col + 1];
                if (mode == 0) { v0 *= SCALING_F; v1 *= SCALING_F; }
                if (mode <= 1) {
                    int t = row >> 1, bb = row & 1;          // row = t*B + b
                    int z = bb * NH + (col >> 6);            // z = b*H + h
                    *(float2*)&out[((size_t)(z * TDIM + t) << 6) + (col & 63)]
                        = make_float2(v0, v1);
                } else {
                    *(float2*)&out[(size_t)row * EDIM + col] = make_float2(v0, v1);
                }
            }
        }
    }
}

// q/k projections in ONE launch: gridDim.z = 2 selects the problem
__global__ __launch_bounds__(256, 2) void qkv_gemm_kernel(
    const float* Xq, const float* Xk, const float* Xv,
    const float* Wq, const float* Wk, const float* Wv,
    const float* bq, const float* bk, const float* bv,
    float* oq, float* ok, float* ov)
{
    extern __shared__ float gsm[];
    const int zz = blockIdx.z;
    const float* X = (zz == 0) ? Xq : (zz == 1) ? Xk : Xv;
    const float* W = (zz == 0) ? Wq : (zz == 1) ? Wk : Wv;
    const float* B = (zz == 0) ? bq : (zz == 1) ? bk : bv;
    float*       O = (zz == 0) ? oq : (zz == 1) ? ok : ov;
    gemm_body(X, W, B, O, (zz == 0) ? 0 : 1, gsm, blockIdx.x, blockIdx.y);
}

__global__ __launch_bounds__(256, 2) void gemm_tf32_kernel(
    const float* __restrict__ X, const float* __restrict__ W,
    const float* __restrict__ bias, float* __restrict__ out, int mode)
{
    extern __shared__ float gsm[];
    gemm_body(X, W, bias, out, mode, gsm, blockIdx.x, blockIdx.y);
}

// ---------------- score body: raw scores = Q @ K^T (128x128 tile) ------------
#define QS2 68

__device__ __forceinline__ void score_body(
    const float* __restrict__ qs, const float* __restrict__ ks,
    float* __restrict__ wout, int sx, int sy, int z, float* ssm)
{
    float* Qs = ssm;               // [128][QS2]
    float* Ks = ssm + 128 * QS2;   // [128][QS2]

    const int tid  = threadIdx.x;
    const int lane = tid & 31, wid = tid >> 5;
    const int wm = wid >> 2, wn = wid & 3;      // 2 x 4 warps, 64x32 tiles
    const int lr = lane >> 2, lc = lane & 3;
    const int s0 = sx * 128;
    const int t0 = sy * 128;

    const float* qg = qs + ((size_t)z * TDIM + t0) * HD;
    const float* kg = ks + ((size_t)z * SDIM + s0) * HD;

    #pragma unroll
    for (int i = 0; i < 8; i++) {             // 2048 float4 per tile
        int idx = tid + i * 256;
        int row = idx >> 4, c4 = (idx & 15) * 4;
        cpa16(s2u(&Qs[row * QS2 + c4]), qg + (size_t)row * HD + c4);
        cpa16(s2u(&Ks[row * QS2 + c4]), kg + (size_t)row * HD + c4);
    }
    CPA_COMMIT(); CPA_WAIT0();
    __syncthreads();

    float acc[4][4][4];
    #pragma unroll
    for (int i = 0; i < 4; i++)
        #pragma unroll
        for (int j = 0; j < 4; j++)
            #pragma unroll
            for (int r = 0; r < 4; r++) acc[i][j][r] = 0.f;

    #pragma unroll
    for (int kk = 0; kk < 8; kk++) {
        const int ko = kk * 8;
        uint32_t a[4][4], b[4][2];
        #pragma unroll
        for (int mf = 0; mf < 4; mf++) {
            int m = wm * 64 + mf * 16;
            a[mf][0] = f2tf32(Qs[(m + lr    ) * QS2 + ko + lc    ]);
            a[mf][1] = f2tf32(Qs[(m + lr + 8) * QS2 + ko + lc    ]);
            a[mf][2] = f2tf32(Qs[(m + lr    ) * QS2 + ko + lc + 4]);
            a[mf][3] = f2tf32(Qs[(m + lr + 8) * QS2 + ko + lc + 4]);
        }
        #pragma unroll
        for (int nf = 0; nf < 4; nf++) {
            int n = wn * 32 + nf * 8;
            b[nf][0] = f2tf32(Ks[(n + lr) * QS2 + ko + lc    ]);
            b[nf][1] = f2tf32(Ks[(n + lr) * QS2 + ko + lc + 4]);
        }
        #pragma unroll
        for (int mf = 0; mf < 4; mf++)
            #pragma unroll
            for (int nf = 0; nf < 4; nf++)
                mma_tf32(acc[mf][nf], a[mf], b[nf]);
    }

    float* wbase = wout + ((size_t)z * TDIM + t0) * SDIM;
    #pragma unroll
    for (int mf = 0; mf < 4; mf++) {
        #pragma unroll
        for (int nf = 0; nf < 4; nf++) {
            #pragma unroll
            for (int rp = 0; rp < 2; rp++) {
                int row = wm * 64 + mf * 16 + lr + rp * 8;
                int col = s0 + wn * 32 + nf * 8 + 2 * lc;
                *(float2*)&wbase[(size_t)row * SDIM + col]
                    = make_float2(acc[mf][nf][rp*2], acc[mf][nf][rp*2+1]);
            }
        }
    }
}

// ---------------- combined launch: V-projection blocks + score blocks --------
// Blocks 0..255: V projection (tensor-bound). Blocks 256..8447: score tiles
// (write-bound). V blocks scheduled first so they overlap score execution.
__global__ __launch_bounds__(256, 2) void score_v_kernel(
    const float* __restrict__ qs, const float* __restrict__ ks,
    float* __restrict__ wout,
    const float* __restrict__ Xv, const float* __restrict__ Wv,
    const float* __restrict__ bv, float* __restrict__ ov)
{
    extern __shared__ float smc[];
    const int id = blockIdx.x;
    if (id < 256) {
        gemm_body(Xv, Wv, bv, ov, 1, smc, id & 7, id >> 3);
    } else {
        const int sid = id - 256;
        // sx fastest, then sy, then z: consecutive blocks share (z, t-row)
        score_body(qs, ks, wout, sid & 15, (sid >> 4) & 15, sid >> 8, smc);
    }
}

// ---------------- softmax: in-place mask + threshold + normalize -------------
// Warp per row; 8 rows per CTA. Row (2048 fp32) held in 64 regs per lane.
__global__ __launch_bounds__(256) void softmax_kernel(
    float* __restrict__ wts, const int* __restrict__ mask)
{
    const int lane = threadIdx.x & 31, w = threadIdx.x >> 5;
    const int t = blockIdx.x * 8 + w;
    const int z = blockIdx.y;
    const float NEG = __int_as_float(0xff800000);

    float* row = wts + ((size_t)z * TDIM + t) * SDIM;
    const int* mrow = mask + (size_t)t * SDIM;

    float sv[64];
    float mx = NEG;
    #pragma unroll
    for (int j = 0; j < 16; j++) {
        int col = j * 128 + lane * 4;
        float4 s = *(const float4*)&row[col];
        int4  mm = *(const int4*)&mrow[col];
        sv[4*j+0] = mm.x ? s.x : NEG;
        sv[4*j+1] = mm.y ? s.y : NEG;
        sv[4*j+2] = mm.z ? s.z : NEG;
        sv[4*j+3] = mm.w ? s.w : NEG;
        mx = fmaxf(mx, fmaxf(fmaxf(sv[4*j], sv[4*j+1]), fmaxf(sv[4*j+2], sv[4*j+3])));
    }
    #pragma unroll
    for (int off = 16; off; off >>= 1)
        mx = fmaxf(mx, __shfl_xor_sync(0xffffffffu, mx, off));

    float sum = 0.f;
    #pragma unroll
    for (int j = 0; j < 64; j++) {
        float d = sv[j] - mx;
        float e = (d >= -D_THRESH_F) ? __expf(d) : 0.f;
        sv[j] = e;
        sum += e;
    }
    #pragma unroll
    for (int off = 16; off; off >>= 1)
        sum += __shfl_xor_sync(0xffffffffu, sum, off);
    const float ri = 1.f / sum;

    #pragma unroll
    for (int j = 0; j < 16; j++) {
        int col = j * 128 + lane * 4;
        *(float4*)&row[col] = make_float4(sv[4*j]*ri, sv[4*j+1]*ri,
                                          sv[4*j+2]*ri, sv[4*j+3]*ri);
    }
}

// ---------------- AV GEMM: attn_mid = weights @ V ----------------------------
// R10-validated 2-sync double buffer.
#define PS 68
#define AV_SMEM ((2*128*PS + 2*64*PS) * 4)     // 104448 B

__global__ __launch_bounds__(256, 2) void av_gemm_kernel(
    const float* __restrict__ wts, const float* __restrict__ vs,
    float* __restrict__ attn_mid)
{
    extern __shared__ float avm[];
    float* Ps = avm;                  // [2][128][PS]
    float* Vs = avm + 2 * 128 * PS;   // [2][64][PS]

    const int tid  = threadIdx.x;
    const int lane = tid & 31, wid = tid >> 5;
    const int wm = wid >> 1, wn = wid & 1;       // 4 x 2 warps, 32x32 tiles
    const int lr = lane >> 2, lc = lane & 3;
    const int t0 = blockIdx.x * 128;
    const int z  = blockIdx.y;

    const float* pbase = wts + (size_t)z * TDIM * SDIM + (size_t)t0 * SDIM;
    const float* vbase = vs  + (size_t)z * SDIM * HD;

    float acc[2][4][4];
    #pragma unroll
    for (int i = 0; i < 2; i++)
        #pragma unroll
        for (int j = 0; j < 4; j++)
            #pragma unroll
            for (int r = 0; r < 4; r++) acc[i][j][r] = 0.f;

    auto stage = [&](int s0, int buf) {
        #pragma unroll
        for (int i = 0; i < 8; i++) {
            int idx = tid + i * 256;
            int row = idx >> 4, c4 = (idx & 15) * 4;
            cpa16(s2u(&Ps[(buf * 128 + row) * PS + c4]),
                  pbase + (size_t)row * SDIM + s0 + c4);
        }
        #pragma unroll
        for (int i = 0; i < 4; i++) {
            int idx = tid + i * 256;
            int row = idx >> 4, c4 = (idx & 15) * 4;
            cpa16(s2u(&Vs[(buf * 64 + row) * PS + c4]),
                  vbase + (size_t)(s0 + row) * HD + c4);
        }
        CPA_COMMIT();
    };

    stage(0, 0);
    for (int c = 0; c < 32; c++) {
        __syncthreads();
        if (c < 31) { stage((c + 1) * 64, (c + 1) & 1); CPA_WAIT1(); }
        else        { CPA_WAIT0(); }
        __syncthreads();
        const float* Pb = Ps + (c & 1) * 128 * PS;
        const float* Vb = Vs + (c & 1) * 64 * PS;
        #pragma unroll
        for (int kk = 0; kk < 8; kk++) {
            const int ko = kk * 8;
            uint32_t a[2][4], b[4][2];
            #pragma unroll
            for (int mf = 0; mf < 2; mf++) {
                int m = wm * 32 + mf * 16;
                a[mf][0] = f2tf32(Pb[(m + lr    ) * PS + ko + lc    ]);
                a[mf][1] = f2tf32(Pb[(m + lr + 8) * PS + ko + lc    ]);
                a[mf][2] = f2tf32(Pb[(m + lr    ) * PS + ko + lc + 4]);
                a[mf][3] = f2tf32(Pb[(m + lr + 8) * PS + ko + lc + 4]);
            }
            #pragma unroll
            for (int nf = 0; nf < 4; nf++) {
                int n = wn * 32 + nf * 8;
                b[nf][0] = f2tf32(Vb[(ko + lc    ) * PS + n + lr]);
                b[nf][1] = f2tf32(Vb[(ko + lc + 4) * PS + n + lr]);
            }
            #pragma unroll
            for (int mf = 0; mf < 2; mf++)
                #pragma unroll
                for (int nf = 0; nf < 4; nf++)
                    mma_tf32(acc[mf][nf], a[mf], b[nf]);
        }
    }

    const int bb = z >> 4, hh = z & 15;
    #pragma unroll
    for (int mf = 0; mf < 2; mf++) {
        #pragma unroll
        for (int nf = 0; nf < 4; nf++) {
            #pragma unroll
            for (int rp = 0; rp < 2; rp++) {
                int t   = t0 + wm * 32 + mf * 16 + lr + rp * 8;
                int col = wn * 32 + nf * 8 + 2 * lc;
                *(float2*)&attn_mid[((size_t)(t * BSZ + bb)) * EDIM + hh * 64 + col]
                    = make_float2(acc[mf][nf][rp*2], acc[mf][nf][rp*2+1]);
            }
        }
    }
}

// ---------------- fallback attention (write_w == 0 only) ---------------------
#define SC_STRIDE 2052
#define KV_STRIDE 72
#define SC_FLOATS (16 * SC_STRIDE)
#define KV_FLOATS (2 * 128 * KV_STRIDE)
#define ATTN_SMEM ((SC_FLOATS + KV_FLOATS + 1024 + 256 + 16 + 16) * 4)

__global__ __launch_bounds__(512, 1) void attn_kernel(
    const float* __restrict__ qs, const float* __restrict__ ks,
    const float* __restrict__ vs, const int* __restrict__ mask,
    float* __restrict__ attn_mid)
{
    extern __shared__ float sm[];
    float* sc     = sm;
    float* kvb    = sm + SC_FLOATS;
    float* pacc   = kvb + KV_FLOATS;
    float* red    = pacc + 1024;
    float* rowmax = red + 256;
    float* rinvs  = rowmax + 16;

    const int tid = threadIdx.x, lane = tid & 31, w = tid >> 5;
    const int lr = lane >> 2, lc = lane & 3;
    const int t0 = blockIdx.x * 16;
    const int z  = blockIdx.y;
    const float NEG = __int_as_float(0xff800000);

    uint32_t aq[8][4];
    {
        const float* qg = qs + ((size_t)(z * TDIM + t0)) * HD;
        #pragma unroll
        for (int kk = 0; kk < 8; kk++) {
            aq[kk][0] = f2tf32(qg[ lr      * 64 + kk*8 + lc    ]);
            aq[kk][1] = f2tf32(qg[(lr + 8) * 64 + kk*8 + lc    ]);
            aq[kk][2] = f2tf32(qg[ lr      * 64 + kk*8 + lc + 4]);
            aq[kk][3] = f2tf32(qg[(lr + 8) * 64 + kk*8 + lc + 4]);
        }
    }

    auto stageKV = [&](const float* src, int s0, int buf) {
        #pragma unroll
        for (int i = 0; i < 4; i++) {
            int idx = tid + i * 512;
            int row = idx >> 4, c4 = (idx & 15) * 4;
            cpa16(s2u(&kvb[(buf * 128 + row) * KV_STRIDE + c4]),
                  src + (size_t)(s0 + row) * HD + c4);
        }
        CPA_COMMIT();
    };

    float mx0 = NEG, mx1 = NEG;
    const float* kbase = ks + (size_t)z * SDIM * HD;
    stageKV(kbase, 0, 0);
    for (int c = 0; c < 16; c++) {
        const int s0 = c * 128;
        __syncthreads();
        if (c < 15) { stageKV(kbase, s0 + 128, (c + 1) & 1); CPA_WAIT1(); }
        else        { CPA_WAIT0(); }
        __syncthreads();

        const int col0 = s0 + w * 8 + 2 * lc;
        int2 m0 = *(const int2*)(mask + (size_t)(t0 + lr    ) * SDIM + col0);
        int2 m1 = *(const int2*)(mask + (size_t)(t0 + lr + 8) * SDIM + col0);

        const float* kb = kvb + (c & 1) * 128 * KV_STRIDE;
        float cacc[4] = {0.f, 0.f, 0.f, 0.f};
        #pragma unroll
        for (int kk = 0; kk < 8; kk++) {
            uint32_t b[2];
            b[0] = f2tf32(kb[(w * 8 + lr) * KV_STRIDE + kk*8 + lc    ]);
            b[1] = f2tf32(kb[(w * 8 + lr) * KV_STRIDE + kk*8 + lc + 4]);
            mma_tf32(cacc, aq[kk], b);
        }
        float v0 = (m0.x == 0) ? NEG : cacc[0];
        float v1 = (m0.y == 0) ? NEG : cacc[1];
        float v2 = (m1.x == 0) ? NEG : cacc[2];
        float v3 = (m1.y == 0) ? NEG : cacc[3];
        *(float2*)&sc[ lr      * SC_STRIDE + col0] = make_float2(v0, v1);
        *(float2*)&sc[(lr + 8) * SC_STRIDE + col0] = make_float2(v2, v3);
        mx0 = fmaxf(mx0, fmaxf(v0, v1));
        mx1 = fmaxf(mx1, fmaxf(v2, v3));
    }

    mx0 = fmaxf(mx0, __shfl_xor_sync(0xffffffffu, mx0, 1));
    mx0 = fmaxf(mx0, __shfl_xor_sync(0xffffffffu, mx0, 2));
    mx1 = fmaxf(mx1, __shfl_xor_sync(0xffffffffu, mx1, 1));
    mx1 = fmaxf(mx1, __shfl_xor_sync(0xffffffffu, mx1, 2));
    if (lc == 0) { red[w * 16 + lr] = mx0; red[w * 16 + lr + 8] = mx1; }
    __syncthreads();
    if (tid < 16) {
        float m = red[tid];
        #pragma unroll
        for (int i = 1; i < 16; i++) m = fmaxf(m, red[i * 16 + tid]);
        rowmax[tid] = m;
    }
    __syncthreads();

    {
        const int row = w;
        const float m = rowmax[row];
        float sum = 0.f;
        #pragma unroll 4
        for (int col = lane * 4; col < SDIM; col += 128) {
            float4 s = *(float4*)&sc[row * SC_STRIDE + col];
            float e0 = (s.x - m >= -D_THRESH_F) ? __expf(s.x - m) : 0.f;
            float e1 = (s.y - m >= -D_THRESH_F) ? __expf(s.y - m) : 0.f;
            float e2 = (s.z - m >= -D_THRESH_F) ? __expf(s.z - m) : 0.f;
            float e3 = (s.w - m >= -D_THRESH_F) ? __expf(s.w - m) : 0.f;
            *(float4*)&sc[row * SC_STRIDE + col] = make_float4(e0, e1, e2, e3);
            sum += (e0 + e1) + (e2 + e3);
        }
        #pragma unroll
        for (int off = 16; off; off >>= 1)
            sum += __shfl_xor_sync(0xffffffffu, sum, off);
        if (lane == 0) rinvs[row] = 1.f / sum;
    }

    __syncthreads();
    const int nOct  = w & 7;
    const int kHalf = w >> 3;
    float acc[4] = {0.f, 0.f, 0.f, 0.f};
    const float* vbase = vs + (size_t)z * SDIM * HD;
    stageKV(vbase, 0, 0);
    for (int c = 0; c < 16; c++) {
        const int s0 = c * 128;
        __syncthreads();
        if (c < 15) { stageKV(vbase, s0 + 128, (c + 1) & 1); CPA_WAIT1(); }
        else        { CPA_WAIT0(); }
        __syncthreads();
        const float* vb = kvb + (c & 1) * 128 * KV_STRIDE;
        #pragma unroll
        for (int j = 0; j < 8; j++) {
            const int kk = kHalf * 8 + j;
            const int kg = s0 + kk * 8;
            uint32_t a[4], b[2];
            a[0] = f2tf32(sc[ lr      * SC_STRIDE + kg + lc    ]);
            a[1] = f2tf32(sc[(lr + 8) * SC_STRIDE + kg + lc    ]);
            a[2] = f2tf32(sc[ lr      * SC_STRIDE + kg + lc + 4]);
            a[3] = f2tf32(sc[(lr + 8) * SC_STRIDE + kg + lc + 4]);
            b[0] = f2tf32(vb[(kk*8 + lc    ) * KV_STRIDE + nOct * 8 + lr]);
            b[1] = f2tf32(vb[(kk*8 + lc + 4) * KV_STRIDE + nOct * 8 + lr]);
            mma_tf32(acc, a, b);
        }
    }
    if (kHalf == 1) {
        #pragma unroll
        for (int r = 0; r < 4; r++) pacc[nOct * 128 + lane * 4 + r] = acc[r];
    }
    __syncthreads();
    if (kHalf == 0) {
        const int bb = z >> 4, hh = z & 15;
        #pragma unroll
        for (int rp = 0; rp < 2; rp++) {
            int row  = lr + rp * 8;
            int colh = nOct * 8 + 2 * lc;
            float ri = rinvs[row];
            float v0 = (acc[rp*2+0] + pacc[nOct * 128 + lane * 4 + rp*2+0]) * ri;
            float v1 = (acc[rp*2+1] + pacc[nOct * 128 + lane * 4 + rp*2+1]) * ri;
            int t = t0 + row;
            *(float2*)&attn_mid[((size_t)(t * BSZ + bb)) * EDIM + hh * 64 + colh]
                = make_float2(v0, v1);
        }
    }
}

// ---------------- launcher ----------------------------------------------------
extern "C" void kernel_launch(void* const* d_in, const int* in_sizes, int n_in,
                              void* d_out, int out_size) {
    const float* query = (const float*)d_in[0];
    const float* key   = (const float*)d_in[1];
    const float* value = (const float*)d_in[2];
    const int*   mask  = (const int*)  d_in[3];
    const float* Wq = (const float*)d_in[4];
    const float* bq = (const float*)d_in[5];
    const float* Wk = (const float*)d_in[6];
    const float* bk = (const float*)d_in[7];
    const float* Wv = (const float*)d_in[8];
    const float* bv = (const float*)d_in[9];
    const float* Wo = (const float*)d_in[10];
    const float* bo = (const float*)d_in[11];

    float *pq, *pk, *pv, *pmid, *psink;
    cudaGetSymbolAddress((void**)&pq,    g_q);
    cudaGetSymbolAddress((void**)&pk,    g_k);
    cudaGetSymbolAddress((void**)&pv,    g_v);
    cudaGetSymbolAddress((void**)&pmid,  g_mid);
    cudaGetSymbolAddress((void**)&psink, g_sink);

    const long long ATTN_N = (long long)TDIM * BSZ * EDIM;       // 4,194,304
    const long long WTS_N  = (long long)NZ * TDIM * SDIM;        // 134,217,728
    float* out = (float*)d_out;
    float* out_attn = out;
    float* out_w    = nullptr;
    int write_w = 0;
    long long osz = (long long)out_size;
    if (osz >= ATTN_N + WTS_N)      { out_attn = out; out_w = out + ATTN_N; write_w = 1; }
    else if (osz == WTS_N)          { out_attn = psink; out_w = out; write_w = 1; }
    else                            { out_attn = out; write_w = 0; out_w = psink; }

    cudaFuncSetAttribute(qkv_gemm_kernel,
                         cudaFuncAttributeMaxDynamicSharedMemorySize, GEMM_SMEM);
    cudaFuncSetAttribute(gemm_tf32_kernel,
                         cudaFuncAttributeMaxDynamicSharedMemorySize, GEMM_SMEM);
    cudaFuncSetAttribute(score_v_kernel,
                         cudaFuncAttributeMaxDynamicSharedMemorySize, GEMM_SMEM);
    cudaFuncSetAttribute(attn_kernel,
                         cudaFuncAttributeMaxDynamicSharedMemorySize, ATTN_SMEM);
    cudaFuncSetAttribute(av_gemm_kernel,
                         cudaFuncAttributeMaxDynamicSharedMemorySize, AV_SMEM);

    if (write_w) {
        // q + k projections only
        dim3 gq(EDIM / 128, (TDIM * BSZ) / 128, 2);   // (8, 32, 2)
        qkv_gemm_kernel<<<gq, 256, GEMM_SMEM>>>(
            query, key, value, Wq, Wk, Wv, bq, bk, bv, pq, pk, pv);

        // combined: 256 V-projection blocks (first) + 8192 score tiles
        score_v_kernel<<<256 + (SDIM/128)*(TDIM/128)*NZ, 256, GEMM_SMEM>>>(
            pq, pk, out_w, value, Wv, bv, pv);

        softmax_kernel<<<dim3(TDIM / 8, NZ), 256>>>(out_w, mask);
        av_gemm_kernel<<<dim3(TDIM / 128, NZ), 256, AV_SMEM>>>(out_w, pv, pmid);
    } else {
        dim3 gq(EDIM / 128, (TDIM * BSZ) / 128, 3);
        qkv_gemm_kernel<<<gq, 256, GEMM_SMEM>>>(
            query, key, value, Wq, Wk, Wv, bq, bk, bv, pq, pk, pv);
        attn_kernel<<<dim3(TDIM / 16, NZ), 512, ATTN_SMEM>>>(
            pq, pk, pv, mask, pmid);
    }

    dim3 gg(EDIM / 128, (TDIM * BSZ) / 128);   // (8, 32)
    gemm_tf32_kernel<<<gg, 256, GEMM_SMEM>>>(pmid, Wo, bo, out_attn, 2);
}